// round 15
// baseline (speedup 1.0000x reference)
#include <cuda_runtime.h>
#include <cuda_fp16.h>
#include <mma.h>
#include <math.h>
#include <stdint.h>

using namespace nvcuda;

#define D 128
#define K2 256
#define NMAX 100000
#define EMAX 800000
#define CAP 64

// ---------------- scratch (static device globals; no allocation allowed) ----
__device__ __align__(16) __half g_x16[(size_t)NMAX * D];
__device__ __align__(16) __half g_h16[(size_t)NMAX * D];
__device__ __align__(16) __half g_a16[(size_t)NMAX * D];
__device__ __align__(16) int    g_cnt[NMAX];            // zero-init; reset in gemm2 epilogue
__device__ __align__(16) int2   g_cw[(size_t)NMAX * CAP];   // packed (col, w-bits)
// W fp16 chunked blobs: [layer(2)][chunk(4)][16KB]  (rows of 64 cols, 128B)
__device__ __align__(16) unsigned char g_Wblob[2 * 4 * 16384];

// ---------------- 1) fused fill + prep ----------------------------------------
__global__ void fill_prep_kernel(const int* __restrict__ ei, const float* __restrict__ ew,
                                 const float* __restrict__ X,
                                 const float* __restrict__ W1, const float* __restrict__ W2,
                                 int N, int E) {
    int idx = blockIdx.x * blockDim.x + threadIdx.x;
    if (idx < E) {
        int s = ei[idx];
        int d = ei[E + idx];
        float w = ew[idx];
        int pos = atomicAdd(&g_cnt[s], 1) & (CAP - 1);
        g_cw[(size_t)s * CAP + pos] = make_int2(d, __float_as_int(w));
    }
    int tot4 = N * D / 4;
    if (idx < tot4) {
        float4 v = *(const float4*)(X + (size_t)idx * 4);
        *(__half2*)(g_x16 + (size_t)idx * 4) = __floats2half2_rn(v.x, v.y);
        *(__half2*)(g_x16 + (size_t)idx * 4 + 2) = __floats2half2_rn(v.z, v.w);
    }
    if (idx < 2 * D * K2) {
        int layer = idx >> 15;
        int rem = idx & 32767;
        int n = rem >> 8;        // 0..127 (output row of W)
        int k = rem & 255;       // 0..255
        const float* W = layer ? W2 : W1;
        float a = W[n * K2 + k];
        int chunk = k >> 6;
        int col = k & 63;
        unsigned char* blob = g_Wblob + (size_t)layer * 65536 + (size_t)chunk * 16384;
        *(__half*)(blob + (uint32_t)n * 128 + col * 2) = __float2half_rn(a);
    }
}

// ---------------- gather aggregation: 2 neighbors per warp-iteration ----------
// lanes 0-15 handle neighbor q, lanes 16-31 handle q+1; each lane loads 16B (8 cols).
__global__ void gather16_kernel(const __half* __restrict__ feat16, int N) {
    int gt = blockIdx.x * blockDim.x + threadIdx.x;
    int n = gt >> 5;
    int lane = gt & 31;
    if (n >= N) return;
    int half = lane >> 4;        // 0 or 1
    int laneIn = lane & 15;      // column group: cols laneIn*8 .. +8
    int cnt = min(g_cnt[n], CAP);
    const int2* cwp = g_cw + (size_t)n * CAP;
    float acc0 = 0.f, acc1 = 0.f, acc2 = 0.f, acc3 = 0.f;
    float acc4 = 0.f, acc5 = 0.f, acc6 = 0.f, acc7 = 0.f;
    float wlane = 0.f;
    for (int j0 = 0; j0 < cnt; j0 += 32) {
        int k = min(cnt - j0, 32);
        int myc = 0;
        int mywb = 0;
        if (lane < k) {
            int2 cw = cwp[j0 + lane];
            myc = cw.x;
            mywb = cw.y;
            wlane += __int_as_float(cw.y);
        }
        for (int q = 0; q < k; q += 2) {
            int qq = q + half;
            int c = __shfl_sync(0xffffffffu, myc, qq & 31);
            float w = __int_as_float(__shfl_sync(0xffffffffu, mywb, qq & 31));
            if (qq >= k) w = 0.f;   // odd tail for lanes 16-31
            const uint4* fp = (const uint4*)(feat16 + (size_t)c * D);
            uint4 raw = __ldg(fp + laneIn);
            float2 f0 = __half22float2(*reinterpret_cast<__half2*>(&raw.x));
            float2 f1 = __half22float2(*reinterpret_cast<__half2*>(&raw.y));
            float2 f2 = __half22float2(*reinterpret_cast<__half2*>(&raw.z));
            float2 f3 = __half22float2(*reinterpret_cast<__half2*>(&raw.w));
            acc0 += f0.x * w; acc1 += f0.y * w;
            acc2 += f1.x * w; acc3 += f1.y * w;
            acc4 += f2.x * w; acc5 += f2.y * w;
            acc6 += f3.x * w; acc7 += f3.y * w;
        }
    }
    // combine the two neighbor-halves (lane i <-> lane i+16 hold same columns)
    acc0 += __shfl_xor_sync(0xffffffffu, acc0, 16);
    acc1 += __shfl_xor_sync(0xffffffffu, acc1, 16);
    acc2 += __shfl_xor_sync(0xffffffffu, acc2, 16);
    acc3 += __shfl_xor_sync(0xffffffffu, acc3, 16);
    acc4 += __shfl_xor_sync(0xffffffffu, acc4, 16);
    acc5 += __shfl_xor_sync(0xffffffffu, acc5, 16);
    acc6 += __shfl_xor_sync(0xffffffffu, acc6, 16);
    acc7 += __shfl_xor_sync(0xffffffffu, acc7, 16);
    // warp-reduce weight sum
    float wsum = wlane;
#pragma unroll
    for (int off = 16; off >= 1; off >>= 1)
        wsum += __shfl_xor_sync(0xffffffffu, wsum, off);
    float inv = 1.0f / fmaxf(wsum, 1e-12f);
    if (half == 0) {
        __half2 p0 = __floats2half2_rn(acc0 * inv, acc1 * inv);
        __half2 p1 = __floats2half2_rn(acc2 * inv, acc3 * inv);
        __half2 p2 = __floats2half2_rn(acc4 * inv, acc5 * inv);
        __half2 p3 = __floats2half2_rn(acc6 * inv, acc7 * inv);
        uint4 o;
        o.x = *reinterpret_cast<uint32_t*>(&p0);
        o.y = *reinterpret_cast<uint32_t*>(&p1);
        o.z = *reinterpret_cast<uint32_t*>(&p2);
        o.w = *reinterpret_cast<uint32_t*>(&p3);
        *(uint4*)(g_a16 + (size_t)n * D + laneIn * 8) = o;
    }
}

// ---------------- wmma fp16 GEMM: 64x128 tile, 128 threads, 4 CTAs/SM ---------
// (unchanged from R13 — proven config)
template <bool NORM>
__global__ __launch_bounds__(128, 4)
void wmma_gemm_kernel(const __half* __restrict__ X16,
                      const unsigned char* __restrict__ Wblob,
                      const float* __restrict__ bias,
                      float* __restrict__ out,
                      __half* __restrict__ out16, int N) {
    extern __shared__ char smem[];
    const int LDT = 72;    // fp16 per tile row (144 bytes)
    const int LDC = 132;   // f32 per Cs row
    float* bias_s = (float*)(smem + 33792);
    float* Cs = (float*)smem;

    int tid = threadIdx.x;
    int wid = tid >> 5;          // 0..3 : cols wid*32..+32
    int bm0 = blockIdx.x * 64;

    bias_s[tid] = bias[tid];

    wmma::fragment<wmma::accumulator, 16, 16, 16, float> acc[4][2];
#pragma unroll
    for (int i = 0; i < 4; i++)
#pragma unroll
        for (int j = 0; j < 2; j++) wmma::fill_fragment(acc[i][j], 0.0f);

    for (int c = 0; c < 4; c++) {
        bool isAgg = (c >= 2);
        int kbyte = (c & 1) * 128;
        const __half* A = isAgg ? g_a16 : X16;

#pragma unroll
        for (int p = 0; p < 4; p++) {
            int idx = p * 128 + tid;        // 0..511
            int row = idx >> 3;
            int seg = idx & 7;
            int n = bm0 + row;
            uint32_t doff = (uint32_t)row * 144 + seg * 16;
            uint4 va = make_uint4(0, 0, 0, 0);
            if (n < N)
                va = *(const uint4*)((const unsigned char*)A + (size_t)n * 256 + kbyte + seg * 16);
            *(uint4*)(smem + doff) = va;
        }
        const unsigned char* wb = Wblob + (size_t)c * 16384;
#pragma unroll
        for (int p = 0; p < 8; p++) {
            int idx = p * 128 + tid;        // 0..1023
            int row = idx >> 3;
            int seg = idx & 7;
            uint32_t doff = (uint32_t)row * 144 + seg * 16;
            *(uint4*)(smem + 9216 + doff) = *(const uint4*)(wb + idx * 16);
        }
        __syncthreads();

        const __half* As = (const __half*)(smem);
        const __half* Bs = (const __half*)(smem + 9216);

#pragma unroll
        for (int ks = 0; ks < 4; ks++) {
            wmma::fragment<wmma::matrix_b, 16, 16, 16, __half, wmma::col_major> bf[2];
#pragma unroll
            for (int j = 0; j < 2; j++) {
                int n0 = wid * 32 + j * 16;
                wmma::load_matrix_sync(bf[j], Bs + n0 * LDT + ks * 16, LDT);
            }
#pragma unroll
            for (int i = 0; i < 4; i++) {
                wmma::fragment<wmma::matrix_a, 16, 16, 16, __half, wmma::row_major> af;
                wmma::load_matrix_sync(af, As + (i * 16) * LDT + ks * 16, LDT);
#pragma unroll
                for (int j = 0; j < 2; j++)
                    wmma::mma_sync(acc[i][j], af, bf[j], acc[i][j]);
            }
        }
        __syncthreads();
    }

#pragma unroll
    for (int i = 0; i < 4; i++)
#pragma unroll
        for (int j = 0; j < 2; j++) {
            wmma::store_matrix_sync(Cs + (i * 16) * LDC + wid * 32 + j * 16,
                                    acc[i][j], LDC, wmma::mem_row_major);
        }
    __syncthreads();

    {
        int row = tid >> 1;          // 0..63
        int half = tid & 1;
        int n = bm0 + row;
        const float* cp = Cs + row * LDC + half * 64;
        const float* bp = bias_s + half * 64;
        float sc = 1.0f;
        if (NORM) {
            float ss = 0.f;
#pragma unroll
            for (int q = 0; q < 16; q++) {
                float4 v = *(const float4*)(cp + q * 4);
                float4 b = *(const float4*)(bp + q * 4);
                float a0 = fmaxf(v.x + b.x, 0.f), a1 = fmaxf(v.y + b.y, 0.f);
                float a2 = fmaxf(v.z + b.z, 0.f), a3 = fmaxf(v.w + b.w, 0.f);
                ss += a0 * a0 + a1 * a1 + a2 * a2 + a3 * a3;
            }
            ss += __shfl_xor_sync(0xffffffffu, ss, 1);
            sc = 1.0f / fmaxf(sqrtf(ss), 1e-12f);
        }
        if (n < N) {
            if (NORM && half == 0) g_cnt[n] = 0;   // reset for next invocation
#pragma unroll
            for (int q = 0; q < 16; q++) {
                float4 v = *(const float4*)(cp + q * 4);
                float4 b = *(const float4*)(bp + q * 4);
                float4 o;
                o.x = fmaxf(v.x + b.x, 0.f) * sc;
                o.y = fmaxf(v.y + b.y, 0.f) * sc;
                o.z = fmaxf(v.z + b.z, 0.f) * sc;
                o.w = fmaxf(v.w + b.w, 0.f) * sc;
                size_t base = (size_t)n * D + half * 64 + q * 4;
                if (NORM) {
                    *(float4*)(out + base) = o;
                } else {
                    *(__half2*)(out16 + base) = __floats2half2_rn(o.x, o.y);
                    *(__half2*)(out16 + base + 2) = __floats2half2_rn(o.z, o.w);
                }
            }
        }
    }
}

// ---------------- launch ------------------------------------------------------
extern "C" void kernel_launch(void* const* d_in, const int* in_sizes, int n_in,
                              void* d_out, int out_size) {
    const float* x = (const float*)d_in[0];
    const int* ei = (const int*)d_in[1];
    const float* ew = (const float*)d_in[2];
    const float* W1 = (const float*)d_in[3];
    const float* b1 = (const float*)d_in[4];
    const float* W2 = (const float*)d_in[5];
    const float* b2 = (const float*)d_in[6];
    float* out = (float*)d_out;

    int N = in_sizes[0] / D;     // 100000
    int E = in_sizes[2];         // 800000

    __half* x16;  cudaGetSymbolAddress((void**)&x16, g_x16);
    __half* h16;  cudaGetSymbolAddress((void**)&h16, g_h16);
    unsigned char* wblob; cudaGetSymbolAddress((void**)&wblob, g_Wblob);

    size_t smemSz = 34304;
    cudaFuncSetAttribute(wmma_gemm_kernel<false>,
                         cudaFuncAttributeMaxDynamicSharedMemorySize, (int)smemSz);
    cudaFuncSetAttribute(wmma_gemm_kernel<true>,
                         cudaFuncAttributeMaxDynamicSharedMemorySize, (int)smemSz);

    int gemmBlocks = (N + 63) / 64;
    int gatherBlocks = (N * 32 + 255) / 256;
    int fpThreads = N * D / 4;   // 3.2M, covers E and W ranges too

    // 1) fused bucket-fill + x->fp16 + W blobs
    fill_prep_kernel<<<(fpThreads + 255) / 256, 256>>>(ei, ew, x, W1, W2, N, E);
    // 2) layer-1 aggregation -> a16
    gather16_kernel<<<gatherBlocks, 256>>>(x16, N);
    // 3) layer-1 GEMM -> h16
    wmma_gemm_kernel<false><<<gemmBlocks, 128, smemSz>>>(x16, wblob, b1,
                                                         nullptr, h16, N);
    // 4) layer-2 aggregation on h16 -> a16   [4th launch: profiled]
    gather16_kernel<<<gatherBlocks, 256>>>(h16, N);
    // 5) layer-2 GEMM + relu + L2 normalize -> out (+cnt reset)
    wmma_gemm_kernel<true><<<gemmBlocks, 128, smemSz>>>(h16, wblob + 65536,
                                                        b2, out, nullptr, N);
}

// round 17
// speedup vs baseline: 1.0700x; 1.0700x over previous
#include <cuda_runtime.h>
#include <cuda_fp16.h>
#include <mma.h>
#include <math.h>
#include <stdint.h>

using namespace nvcuda;

#define D 128
#define K2 256
#define NMAX 100000
#define EMAX 800000
#define CAP 64

// ---------------- scratch (static device globals; no allocation allowed) ----
__device__ __align__(16) __half g_x16[(size_t)NMAX * D];
__device__ __align__(16) __half g_h16[(size_t)NMAX * D];
__device__ __align__(16) __half g_a16[(size_t)NMAX * D];
__device__ __align__(16) int    g_cnt[NMAX];            // zero-init; reset in gemm2 epilogue
__device__ __align__(16) int2   g_cw[(size_t)NMAX * CAP];   // packed (col, w-bits)
// W fp16 chunk blobs: [layer(2)][chunk(2)][32KB]  (128 rows x 128 cols, 256B rows)
__device__ __align__(16) unsigned char g_Wblob[2 * 2 * 32768];

// ---------------- 1) fused fill + prep ----------------------------------------
__global__ void fill_prep_kernel(const int* __restrict__ ei, const float* __restrict__ ew,
                                 const float* __restrict__ X,
                                 const float* __restrict__ W1, const float* __restrict__ W2,
                                 int N, int E) {
    int idx = blockIdx.x * blockDim.x + threadIdx.x;
    if (idx < E) {
        int s = ei[idx];
        int d = ei[E + idx];
        float w = ew[idx];
        int pos = atomicAdd(&g_cnt[s], 1) & (CAP - 1);
        g_cw[(size_t)s * CAP + pos] = make_int2(d, __float_as_int(w));
    }
    int tot4 = N * D / 4;
    if (idx < tot4) {
        float4 v = *(const float4*)(X + (size_t)idx * 4);
        *(__half2*)(g_x16 + (size_t)idx * 4) = __floats2half2_rn(v.x, v.y);
        *(__half2*)(g_x16 + (size_t)idx * 4 + 2) = __floats2half2_rn(v.z, v.w);
    }
    if (idx < 2 * D * K2) {
        int layer = idx >> 15;
        int rem = idx & 32767;
        int n = rem >> 8;        // 0..127 (output row of W)
        int k = rem & 255;       // 0..255
        const float* W = layer ? W2 : W1;
        float a = W[n * K2 + k];
        int chunk = k >> 7;      // 0..1 (128-col chunks)
        int col = k & 127;
        unsigned char* blob = g_Wblob + (size_t)layer * 65536 + (size_t)chunk * 32768;
        *(__half*)(blob + (uint32_t)n * 256 + col * 2) = __float2half_rn(a);
    }
}

// ---------------- gather aggregation (R13-proven shuffle version) -------------
__global__ void gather16_kernel(const __half* __restrict__ feat16, int N) {
    int gt = blockIdx.x * blockDim.x + threadIdx.x;
    int n = gt >> 5;
    int lane = gt & 31;
    if (n >= N) return;
    int cnt = min(g_cnt[n], CAP);
    const int2* cwp = g_cw + (size_t)n * CAP;
    float4 acc = make_float4(0.f, 0.f, 0.f, 0.f);
    float wsum = 0.f;
    for (int j0 = 0; j0 < cnt; j0 += 32) {
        int k = min(cnt - j0, 32);
        int myc = 0;
        int mywb = 0;
        if (lane < k) {
            int2 cw = cwp[j0 + lane];
            myc = cw.x;
            mywb = cw.y;
        }
        for (int q = 0; q < k; q++) {
            int c = __shfl_sync(0xffffffffu, myc, q);
            float w = __int_as_float(__shfl_sync(0xffffffffu, mywb, q));
            const uint2* fp = (const uint2*)(feat16 + (size_t)c * D);
            uint2 raw = __ldg(fp + lane);
            float2 f0 = __half22float2(*reinterpret_cast<__half2*>(&raw.x));
            float2 f1 = __half22float2(*reinterpret_cast<__half2*>(&raw.y));
            acc.x += f0.x * w;
            acc.y += f0.y * w;
            acc.z += f1.x * w;
            acc.w += f1.y * w;
            wsum += w;
        }
    }
    float inv = 1.0f / fmaxf(wsum, 1e-12f);
    size_t base = (size_t)n * D + lane * 4;
    *(__half2*)(g_a16 + base) = __floats2half2_rn(acc.x * inv, acc.y * inv);
    *(__half2*)(g_a16 + base + 2) = __floats2half2_rn(acc.z * inv, acc.w * inv);
}

// ---------------- wmma fp16 GEMM: 64x128 tile, 2 K-chunks of 128 --------------
// C[n][j] = relu( sum_k A[n][k] * W[j][k] + bias[j] ),  A = [X16 | A16] fp16
// chunk 0: A = X16 (k 0..127), chunk 1: A = g_a16 (k 128..255).
// LDT=136 (272B rows, 16B-aligned; 8-row ldmatrix hits banks {0,4,..,28}).
// SMEM (bytes): As@0 (64x272=17408), Bs@17408 (128x272=34816), bias@52224 (512);
//               total 52736.  Cs (64x132 f32=33792) reuses @0 after compute.
template <bool NORM>
__global__ __launch_bounds__(128, 4)
void wmma_gemm_kernel(const __half* __restrict__ X16,
                      const unsigned char* __restrict__ Wblob,
                      const float* __restrict__ bias,
                      float* __restrict__ out,
                      __half* __restrict__ out16, int N) {
    extern __shared__ char smem[];
    const int LDT = 136;   // fp16 per tile row (272 bytes, 16B-aligned stride)
    const int LDC = 132;   // f32 per Cs row
    float* bias_s = (float*)(smem + 52224);
    float* Cs = (float*)smem;

    int tid = threadIdx.x;
    int wid = tid >> 5;          // 0..3 : cols wid*32..+32
    int bm0 = blockIdx.x * 64;

    bias_s[tid] = bias[tid];

    wmma::fragment<wmma::accumulator, 16, 16, 16, float> acc[4][2];
#pragma unroll
    for (int i = 0; i < 4; i++)
#pragma unroll
        for (int j = 0; j < 2; j++) wmma::fill_fragment(acc[i][j], 0.0f);

    for (int c = 0; c < 2; c++) {
        const __half* A = c ? g_a16 : X16;

        // ---- A copy: 64 rows x 256B fp16 ------------------------------------
#pragma unroll
        for (int p = 0; p < 8; p++) {
            int idx = p * 128 + tid;        // 0..1023
            int row = idx >> 4;             // 0..63
            int seg = idx & 15;             // 0..15
            int n = bm0 + row;
            uint32_t doff = (uint32_t)row * 272 + seg * 16;
            uint4 va = make_uint4(0, 0, 0, 0);
            if (n < N)
                va = *(const uint4*)((const unsigned char*)A + (size_t)n * 256 + seg * 16);
            *(uint4*)(smem + doff) = va;
        }
        // ---- W copy (blob already chunk-ordered): 128 rows x 256B ------------
        const unsigned char* wb = Wblob + (size_t)c * 32768;
#pragma unroll
        for (int p = 0; p < 16; p++) {
            int idx = p * 128 + tid;        // 0..2047
            int row = idx >> 4;
            int seg = idx & 15;
            uint32_t doff = (uint32_t)row * 272 + seg * 16;
            *(uint4*)(smem + 17408 + doff) = *(const uint4*)(wb + idx * 16);
        }
        __syncthreads();

        const __half* As = (const __half*)(smem);
        const __half* Bs = (const __half*)(smem + 17408);

#pragma unroll
        for (int ks = 0; ks < 8; ks++) {
            wmma::fragment<wmma::matrix_b, 16, 16, 16, __half, wmma::col_major> bf[2];
#pragma unroll
            for (int j = 0; j < 2; j++) {
                int n0 = wid * 32 + j * 16;
                wmma::load_matrix_sync(bf[j], Bs + n0 * LDT + ks * 16, LDT);
            }
#pragma unroll
            for (int i = 0; i < 4; i++) {
                wmma::fragment<wmma::matrix_a, 16, 16, 16, __half, wmma::row_major> af;
                wmma::load_matrix_sync(af, As + (i * 16) * LDT + ks * 16, LDT);
#pragma unroll
                for (int j = 0; j < 2; j++)
                    wmma::mma_sync(acc[i][j], af, bf[j], acc[i][j]);
            }
        }
        __syncthreads();
    }

#pragma unroll
    for (int i = 0; i < 4; i++)
#pragma unroll
        for (int j = 0; j < 2; j++) {
            wmma::store_matrix_sync(Cs + (i * 16) * LDC + wid * 32 + j * 16,
                                    acc[i][j], LDC, wmma::mem_row_major);
        }
    __syncthreads();

    {
        int row = tid >> 1;          // 0..63
        int half = tid & 1;
        int n = bm0 + row;
        const float* cp = Cs + row * LDC + half * 64;
        const float* bp = bias_s + half * 64;
        float sc = 1.0f;
        if (NORM) {
            float ss = 0.f;
#pragma unroll
            for (int q = 0; q < 16; q++) {
                float4 v = *(const float4*)(cp + q * 4);
                float4 b = *(const float4*)(bp + q * 4);
                float a0 = fmaxf(v.x + b.x, 0.f), a1 = fmaxf(v.y + b.y, 0.f);
                float a2 = fmaxf(v.z + b.z, 0.f), a3 = fmaxf(v.w + b.w, 0.f);
                ss += a0 * a0 + a1 * a1 + a2 * a2 + a3 * a3;
            }
            ss += __shfl_xor_sync(0xffffffffu, ss, 1);
            sc = 1.0f / fmaxf(sqrtf(ss), 1e-12f);
        }
        if (n < N) {
            if (NORM && half == 0) g_cnt[n] = 0;   // reset for next invocation
#pragma unroll
            for (int q = 0; q < 16; q++) {
                float4 v = *(const float4*)(cp + q * 4);
                float4 b = *(const float4*)(bp + q * 4);
                float4 o;
                o.x = fmaxf(v.x + b.x, 0.f) * sc;
                o.y = fmaxf(v.y + b.y, 0.f) * sc;
                o.z = fmaxf(v.z + b.z, 0.f) * sc;
                o.w = fmaxf(v.w + b.w, 0.f) * sc;
                size_t base = (size_t)n * D + half * 64 + q * 4;
                if (NORM) {
                    *(float4*)(out + base) = o;
                } else {
                    *(__half2*)(out16 + base) = __floats2half2_rn(o.x, o.y);
                    *(__half2*)(out16 + base + 2) = __floats2half2_rn(o.z, o.w);
                }
            }
        }
    }
}

// ---------------- launch ------------------------------------------------------
extern "C" void kernel_launch(void* const* d_in, const int* in_sizes, int n_in,
                              void* d_out, int out_size) {
    const float* x = (const float*)d_in[0];
    const int* ei = (const int*)d_in[1];
    const float* ew = (const float*)d_in[2];
    const float* W1 = (const float*)d_in[3];
    const float* b1 = (const float*)d_in[4];
    const float* W2 = (const float*)d_in[5];
    const float* b2 = (const float*)d_in[6];
    float* out = (float*)d_out;

    int N = in_sizes[0] / D;     // 100000
    int E = in_sizes[2];         // 800000

    __half* x16;  cudaGetSymbolAddress((void**)&x16, g_x16);
    __half* h16;  cudaGetSymbolAddress((void**)&h16, g_h16);
    unsigned char* wblob; cudaGetSymbolAddress((void**)&wblob, g_Wblob);

    size_t smemSz = 52736;
    cudaFuncSetAttribute(wmma_gemm_kernel<false>,
                         cudaFuncAttributeMaxDynamicSharedMemorySize, (int)smemSz);
    cudaFuncSetAttribute(wmma_gemm_kernel<true>,
                         cudaFuncAttributeMaxDynamicSharedMemorySize, (int)smemSz);

    int gemmBlocks = (N + 63) / 64;
    int gatherBlocks = (N * 32 + 255) / 256;
    int fpThreads = N * D / 4;   // 3.2M, covers E and W ranges too

    // 1) fused bucket-fill + x->fp16 + W blobs
    fill_prep_kernel<<<(fpThreads + 255) / 256, 256>>>(ei, ew, x, W1, W2, N, E);
    // 2) layer-1 aggregation -> a16
    gather16_kernel<<<gatherBlocks, 256>>>(x16, N);
    // 3) layer-1 GEMM -> h16
    wmma_gemm_kernel<false><<<gemmBlocks, 128, smemSz>>>(x16, wblob, b1,
                                                         nullptr, h16, N);
    // 4) layer-2 aggregation on h16 -> a16   [4th launch: profiled]
    gather16_kernel<<<gatherBlocks, 256>>>(h16, N);
    // 5) layer-2 GEMM + relu + L2 normalize -> out (+cnt reset)
    wmma_gemm_kernel<true><<<gemmBlocks, 128, smemSz>>>(h16, wblob + 65536,
                                                        b2, out, nullptr, N);
}